// round 15
// baseline (speedup 1.0000x reference)
#include <cuda_runtime.h>
#include <cuda_fp16.h>
#include <cstdint>
#include <math.h>

#define BATCH 8192
#define DIM 768
#define NELEM (BATCH * DIM)      /* 6291456 */
#define NLAYERS 4
#define WSIZE (NLAYERS * DIM * DIM)   /* 2359296 per net */

// GEMM tiling
#define BM 128
#define BN 64
#define BK 32
#define NCHUNKS (DIM / BK)       /* 24 */
#define NTILES (DIM / BN)        /* 12 */
#define MTILES (2 * BATCH / BM)  /* 128 total; 64 per net */
#define CTAS_PER_NET (NTILES * (MTILES / 2))   /* 768 */
#define NSTAGES 3
#define STAGE_BYTES 24576
#define STAGE_HALVES 12288
#define GEMM_SMEM (NSTAGES * STAGE_BYTES)   /* 73728 */

#define OPSCALE 32.0f
#define INVSCALE (1.0f / 1024.0f)

// ---------------- device scratch ----------------
__device__ __align__(16) float  g_x[2 * (size_t)NELEM];
__device__ __align__(16) __half g_xhi[2 * (size_t)NELEM];
__device__ __align__(16) __half g_xlo[2 * (size_t)NELEM];
__device__ __align__(16) float  g_cross[2 * (size_t)NELEM];
__device__ double g_part[NTILES * MTILES][2];   /* 1536; net n at [n*768, n*768+768) */
__device__ float  g_mv[4];
__device__ double g_hpart[1024][2];
__device__ unsigned g_ctr[2];                   /* zero-init; reset by last CTA */
__device__ __align__(16) __half g_whi[2 * (size_t)WSIZE];
__device__ __align__(16) __half g_wlo[2 * (size_t)WSIZE];

// ---------------- helpers ----------------
__device__ __forceinline__ uint32_t smem_u32(const void* p) {
    uint32_t a;
    asm("{ .reg .u64 t; cvta.to.shared.u64 t, %1; cvt.u32.u64 %0, t; }" : "=r"(a) : "l"(p));
    return a;
}
#define CP_ASYNC16(dst, src) \
    asm volatile("cp.async.cg.shared.global [%0], [%1], 16;" :: "r"(dst), "l"(src) : "memory")
#define CP_COMMIT() asm volatile("cp.async.commit_group;" ::: "memory")
#define CP_WAIT(n)  asm volatile("cp.async.wait_group %0;" :: "n"(n) : "memory")

__device__ __forceinline__ uint32_t pack2(__half a, __half b) {
    __half2 h2 = __halves2half2(a, b);
    uint32_t u;
    asm("mov.b32 %0, %1;" : "=r"(u) : "r"(*reinterpret_cast<uint32_t*>(&h2)));
    return u;
}

__device__ __forceinline__ void split_f16(float v, __half& h, __half& l) {
    float vs = v * OPSCALE;
    h = __float2half_rn(vs);
    l = __float2half_rn(vs - __half2float(h));
}

__device__ __forceinline__ void mma_f16(float* d, const uint32_t* a, const uint32_t* b) {
    asm volatile(
        "mma.sync.aligned.m16n8k16.row.col.f32.f16.f16.f32 "
        "{%0,%1,%2,%3},{%4,%5,%6,%7},{%8,%9},{%0,%1,%2,%3};"
        : "+f"(d[0]), "+f"(d[1]), "+f"(d[2]), "+f"(d[3])
        : "r"(a[0]), "r"(a[1]), "r"(a[2]), "r"(a[3]), "r"(b[0]), "r"(b[1]));
}

__device__ __forceinline__ int sw_off(int r, int k) {
    return r * 32 + (k ^ ((r & 6) << 2));
}
__device__ __forceinline__ uint32_t ldh2(const __half* base, int r, int k) {
    return *reinterpret_cast<const uint32_t*>(base + sw_off(r, k));
}

// ---------------- W split (x4 vectorized) ----------------
__global__ void split_w_kernel(const float* __restrict__ Wd, const float* __restrict__ Ws) {
    size_t e = ((size_t)blockIdx.x * blockDim.x + threadIdx.x) * 4;
    if (e >= 2 * (size_t)WSIZE) return;
    float4 v = (e < WSIZE) ? *reinterpret_cast<const float4*>(Wd + e)
                           : *reinterpret_cast<const float4*>(Ws + (e - WSIZE));
    __half h0, h1, h2, h3, l0, l1, l2, l3;
    split_f16(v.x, h0, l0); split_f16(v.y, h1, l1);
    split_f16(v.z, h2, l2); split_f16(v.w, h3, l3);
    uint2 hh, ll;
    hh.x = pack2(h0, h1); hh.y = pack2(h2, h3);
    ll.x = pack2(l0, l1); ll.y = pack2(l2, l3);
    *reinterpret_cast<uint2*>(g_whi + e) = hh;
    *reinterpret_cast<uint2*>(g_wlo + e) = ll;
}

// ---------------- embedding gather + split (both nets) ----------------
__global__ void embed_kernel(const int* __restrict__ xp, const int* __restrict__ xa,
                             const int* __restrict__ xc,
                             const float* __restrict__ E0, const float* __restrict__ E1,
                             const float* __restrict__ E2) {
    int e = (blockIdx.x * blockDim.x + threadIdx.x) * 4;
    if (e >= NELEM) return;
    int b = e / DIM;
    int c = e - b * DIM;
    int s = c >> 7;
    int col = (c & 127) + ((s >= 3) ? 128 : 0);
    int t = (s >= 3) ? (s - 3) : s;
    int row;
    const float* E;
    if (t == 0)      { row = xp[b]; E = E0; }
    else if (t == 1) { row = xa[b]; E = E1; }
    else             { row = xc[b]; E = E2; }
    float4 v = *reinterpret_cast<const float4*>(E + (size_t)row * 256 + col);
    __half h0, h1, h2, h3, l0, l1, l2, l3;
    split_f16(v.x, h0, l0); split_f16(v.y, h1, l1);
    split_f16(v.z, h2, l2); split_f16(v.w, h3, l3);
    uint2 hh, ll;
    hh.x = pack2(h0, h1); hh.y = pack2(h2, h3);
    ll.x = pack2(l0, l1); ll.y = pack2(l2, l3);
    *reinterpret_cast<float4*>(g_x + e) = v;
    *reinterpret_cast<float4*>(g_x + (size_t)NELEM + e) = v;
    *reinterpret_cast<uint2*>(g_xhi + e) = hh;
    *reinterpret_cast<uint2*>(g_xhi + (size_t)NELEM + e) = hh;
    *reinterpret_cast<uint2*>(g_xlo + e) = ll;
    *reinterpret_cast<uint2*>(g_xlo + (size_t)NELEM + e) = ll;
}

// ---------------- mma.sync 3xFP16 GEMM + fused last-CTA stats finalize ----------------
__global__ __launch_bounds__(256, 2)
void gemm_kernel(const float* __restrict__ bd, const float* __restrict__ bs,
                 int layer, int net) {
    extern __shared__ __half smh[];
    const uint32_t sbase = smem_u32(smh);
    const int tid = threadIdx.x;
    const int wid = tid >> 5;
    const int lane = tid & 31;
    const int nt = blockIdx.x;
    const int mt = blockIdx.y + net * (MTILES / 2);
    const int mrow0 = mt * BM;
    const int nbase = nt * BN;
    const float* bias = (net ? bs : bd) + layer * DIM;
    const __half* Ahi_g = g_xhi + (size_t)mrow0 * DIM;
    const __half* Alo_g = g_xlo + (size_t)mrow0 * DIM;
    const __half* Bhi_g = g_whi + (size_t)(net * NLAYERS + layer) * DIM * DIM + (size_t)nbase * DIM;
    const __half* Blo_g = g_wlo + (size_t)(net * NLAYERS + layer) * DIM * DIM + (size_t)nbase * DIM;

    const int wm = wid >> 2;
    const int wn = wid & 3;

    float acc[4][2][4];
    #pragma unroll
    for (int t = 0; t < 4; t++)
        #pragma unroll
        for (int u = 0; u < 2; u++)
            #pragma unroll
            for (int j = 0; j < 4; j++) acc[t][u][j] = 0.0f;

    auto load_chunk = [&](int c, int stage) {
        uint32_t db = sbase + (uint32_t)stage * STAGE_BYTES;
        #pragma unroll
        for (int i = 0; i < 2; i++) {
            int id = tid + i * 256;
            int row = id >> 2, kg = id & 3;
            uint32_t soff = (uint32_t)(row * 64 + 16 * (kg ^ ((row & 6) >> 1)));
            size_t goff = (size_t)row * DIM + c * BK + kg * 8;
            CP_ASYNC16(db + soff,        Ahi_g + goff);
            CP_ASYNC16(db + 8192 + soff, Alo_g + goff);
        }
        {
            int row = tid >> 2, kg = tid & 3;
            uint32_t soff = (uint32_t)(row * 64 + 16 * (kg ^ ((row & 6) >> 1)));
            size_t goff = (size_t)row * DIM + c * BK + kg * 8;
            CP_ASYNC16(db + 16384 + soff, Bhi_g + goff);
            CP_ASYNC16(db + 20480 + soff, Blo_g + goff);
        }
        CP_COMMIT();
    };

    load_chunk(0, 0);
    load_chunk(1, 1);

    for (int c = 0; c < NCHUNKS; c++) {
        if (c + 1 < NCHUNKS) { CP_WAIT(1); } else { CP_WAIT(0); }
        __syncthreads();
        if (c + 2 < NCHUNKS) load_chunk(c + 2, (c + 2) % NSTAGES);

        const __half* Ah = smh + (c % NSTAGES) * STAGE_HALVES;
        const __half* Al = Ah + 4096;
        const __half* Bh = Ah + 8192;
        const __half* Bl = Ah + 10240;

        #pragma unroll
        for (int ks = 0; ks < 2; ks++) {
            const int kb = ks * 16 + 2 * (lane & 3);
            uint32_t ah[4][4], al[4][4], bh[2][2], bl[2][2];
            #pragma unroll
            for (int t = 0; t < 4; t++) {
                int r0 = wm * 64 + t * 16 + (lane >> 2);
                ah[t][0] = ldh2(Ah, r0,     kb);
                ah[t][1] = ldh2(Ah, r0 + 8, kb);
                ah[t][2] = ldh2(Ah, r0,     kb + 8);
                ah[t][3] = ldh2(Ah, r0 + 8, kb + 8);
                al[t][0] = ldh2(Al, r0,     kb);
                al[t][1] = ldh2(Al, r0 + 8, kb);
                al[t][2] = ldh2(Al, r0,     kb + 8);
                al[t][3] = ldh2(Al, r0 + 8, kb + 8);
            }
            #pragma unroll
            for (int u = 0; u < 2; u++) {
                int n0 = wn * 16 + u * 8 + (lane >> 2);
                bh[u][0] = ldh2(Bh, n0, kb);
                bh[u][1] = ldh2(Bh, n0, kb + 8);
                bl[u][0] = ldh2(Bl, n0, kb);
                bl[u][1] = ldh2(Bl, n0, kb + 8);
            }
            #pragma unroll
            for (int t = 0; t < 4; t++)
                #pragma unroll
                for (int u = 0; u < 2; u++) {
                    mma_f16(acc[t][u], ah[t], bh[u]);   // hi*hi
                    mma_f16(acc[t][u], ah[t], bl[u]);   // hi*lo
                    mma_f16(acc[t][u], al[t], bh[u]);   // lo*hi
                }
        }
        __syncthreads();
    }

    // ---- epilogue: unscale + bias -> g_cross, fused fp64 stats ----
    double s = 0.0, q = 0.0;
    #pragma unroll
    for (int t = 0; t < 4; t++) {
        int r0 = mrow0 + wm * 64 + t * 16 + (lane >> 2);
        #pragma unroll
        for (int u = 0; u < 2; u++) {
            int c0 = nbase + wn * 16 + u * 8 + 2 * (lane & 3);
            float b0 = __ldg(&bias[c0]), b1 = __ldg(&bias[c0 + 1]);
            float v0 = fmaf(acc[t][u][0], INVSCALE, b0);
            float v1 = fmaf(acc[t][u][1], INVSCALE, b1);
            float v2 = fmaf(acc[t][u][2], INVSCALE, b0);
            float v3 = fmaf(acc[t][u][3], INVSCALE, b1);
            *reinterpret_cast<float2*>(&g_cross[(size_t)r0 * DIM + c0])       = make_float2(v0, v1);
            *reinterpret_cast<float2*>(&g_cross[(size_t)(r0 + 8) * DIM + c0]) = make_float2(v2, v3);
            s += (double)v0 + (double)v1 + (double)v2 + (double)v3;
            q += (double)v0 * v0 + (double)v1 * v1 + (double)v2 * v2 + (double)v3 * v3;
        }
    }
    #pragma unroll
    for (int o = 16; o; o >>= 1) {
        s += __shfl_down_sync(~0u, s, o);
        q += __shfl_down_sync(~0u, q, o);
    }
    __shared__ double s_ps[8], s_pq[8];
    __shared__ int s_last;
    if (lane == 0) { s_ps[wid] = s; s_pq[wid] = q; }
    __syncthreads();
    if (tid == 0) {
        double S = 0, Q = 0;
        #pragma unroll
        for (int i = 0; i < 8; i++) { S += s_ps[i]; Q += s_pq[i]; }
        int cta = mt * NTILES + nt;
        g_part[cta][0] = S;
        g_part[cta][1] = Q;
        __threadfence();
        unsigned old = atomicAdd(&g_ctr[net], 1u);
        s_last = (old == CTAS_PER_NET - 1);
    }
    __syncthreads();

    // ---- last CTA of this net finalizes mean/scale (deterministic fixed order) ----
    if (s_last) {
        __threadfence();
        __shared__ double sh_s[8], sh_q[8];
        const int base = net * CTAS_PER_NET;
        double ls = 0.0, lq = 0.0;
        #pragma unroll
        for (int it = 0; it < 3; it++) {
            ls += g_part[base + tid + it * 256][0];
            lq += g_part[base + tid + it * 256][1];
        }
        #pragma unroll
        for (int o = 16; o; o >>= 1) {
            ls += __shfl_down_sync(~0u, ls, o);
            lq += __shfl_down_sync(~0u, lq, o);
        }
        if (lane == 0) { sh_s[wid] = ls; sh_q[wid] = lq; }
        __syncthreads();
        if (tid == 0) {
            double S = 0, Q = 0;
            #pragma unroll
            for (int j = 0; j < 8; j++) { S += sh_s[j]; Q += sh_q[j]; }
            double N = (double)NELEM;
            double m = S / N;
            float vf = (float)(Q / N - m * m);
            g_mv[net * 2 + 0] = (float)m;
            g_mv[net * 2 + 1] = (float)(1.0 / sqrt((double)vf + 1e-5));
            g_ctr[net] = 0;          // reset for next launch / graph replay
        }
    }
}

// ---------------- JAX Threefry2x32 (exact, 20 rounds), 4-wide ----------------
__device__ __forceinline__ void threefry4(uint32_t k0, uint32_t k1, unsigned i, uint32_t* bits) {
    uint32_t k2 = k0 ^ k1 ^ 0x1BD11BDAu;
    uint32_t a[4], b[4];
    #pragma unroll
    for (int j = 0; j < 4; j++) { a[j] = k0; b[j] = (i + j) + k1; }
#define TFR4(r) { _Pragma("unroll") for (int j = 0; j < 4; j++) { a[j] += b[j]; b[j] = __funnelshift_l(b[j], b[j], (r)); b[j] ^= a[j]; } }
#define KADD4(ka, kb, inc) { _Pragma("unroll") for (int j = 0; j < 4; j++) { a[j] += (ka); b[j] += (kb) + (inc); } }
    TFR4(13) TFR4(15) TFR4(26) TFR4(6)   KADD4(k1, k2, 1u)
    TFR4(17) TFR4(29) TFR4(16) TFR4(24)  KADD4(k2, k0, 2u)
    TFR4(13) TFR4(15) TFR4(26) TFR4(6)   KADD4(k0, k1, 3u)
    TFR4(17) TFR4(29) TFR4(16) TFR4(24)  KADD4(k1, k2, 4u)
    TFR4(13) TFR4(15) TFR4(26) TFR4(6)   KADD4(k2, k0, 5u)
#undef TFR4
#undef KADD4
    #pragma unroll
    for (int j = 0; j < 4; j++) bits[j] = a[j] ^ b[j];
}

// per-net mask: 4 elements per thread; `layer` controls last-layer split skip
__global__ void mask_kernel(uint32_t k0, uint32_t k1, int net, int layer) {
    unsigned v = blockIdx.x * blockDim.x + threadIdx.x;
    unsigned i = v * 4;                              // [0, NELEM)
    size_t e = (size_t)net * NELEM + i;
    uint32_t bits[4];
    threefry4(k0, k1, i, bits);
    float m = g_mv[net * 2], sc = g_mv[net * 2 + 1];
    float4 c4 = *reinterpret_cast<const float4*>(g_cross + e);
    float4 x4 = *reinterpret_cast<const float4*>(g_x + e);
    float cc[4] = {c4.x, c4.y, c4.z, c4.w};
    float xx[4] = {x4.x, x4.y, x4.z, x4.w};
    #pragma unroll
    for (int j = 0; j < 4; j++) {
        float p = __fdividef(1.0f, 1.0f + __expf(-(cc[j] - m) * sc));
        float u = __uint_as_float((bits[j] >> 9) | 0x3f800000u) - 1.0f;
        xx[j] += (u < p) ? cc[j] : 0.0f;
    }
    *reinterpret_cast<float4*>(g_x + e) = make_float4(xx[0], xx[1], xx[2], xx[3]);
    if (layer != NLAYERS - 1) {
        __half h0, h1, h2, h3, l0, l1, l2, l3;
        split_f16(xx[0], h0, l0); split_f16(xx[1], h1, l1);
        split_f16(xx[2], h2, l2); split_f16(xx[3], h3, l3);
        uint2 hh, ll;
        hh.x = pack2(h0, h1); hh.y = pack2(h2, h3);
        ll.x = pack2(l0, l1); ll.y = pack2(l2, l3);
        *reinterpret_cast<uint2*>(g_xhi + e) = hh;
        *reinterpret_cast<uint2*>(g_xlo + e) = ll;
    }
}

// ---------------- heads + per-row BCE terms ----------------
__device__ __forceinline__ float sigf(float x) { return 1.0f / (1.0f + expf(-x)); }

__global__ void head_kernel(const float* __restrict__ wfd, const float* __restrict__ wfs,
                            const float* __restrict__ bfd, const float* __restrict__ bfs,
                            const float* __restrict__ y_true, float* __restrict__ out) {
    int warp = threadIdx.x >> 5, lane = threadIdx.x & 31;
    int row = blockIdx.x * 8 + warp;
    const float* xd = g_x + (size_t)row * DIM;
    const float* xs = g_x + (size_t)NELEM + (size_t)row * DIM;
    float add = 0.f, ads = 0.f, asd = 0.f, ass = 0.f;
    for (int c = lane; c < DIM; c += 32) {
        float vd = xd[c], vs = xs[c], wd = wfd[c], ws = wfs[c];
        add = fmaf(vd, wd, add); ads = fmaf(vd, ws, ads);
        asd = fmaf(vs, wd, asd); ass = fmaf(vs, ws, ass);
    }
    #pragma unroll
    for (int o = 16; o; o >>= 1) {
        add += __shfl_down_sync(~0u, add, o);
        ads += __shfl_down_sync(~0u, ads, o);
        asd += __shfl_down_sync(~0u, asd, o);
        ass += __shfl_down_sync(~0u, ass, o);
    }
    __shared__ double shd[8], shs[8];
    if (lane == 0) {
        float sdd = sigf(add + bfd[0]);
        float sss = sigf(ass + bfs[0]);
        float sds = sigf(asd + bfd[0]);
        float ssd = sigf(ads + bfs[0]);
        float ypd = 0.5f * (sdd + sss);
        float yps = 0.5f * (sds + ssd);
        out[row] = ypd;
        float y = y_true[row];
        shd[warp] = (double)(-(y * logf(ypd) + (1.0f - y) * logf(1.0f - ypd)));
        shs[warp] = (double)(-(y * logf(yps) + (1.0f - y) * logf(1.0f - yps)));
    }
    __syncthreads();
    if (threadIdx.x == 0) {
        double a = 0, b = 0;
        #pragma unroll
        for (int i = 0; i < 8; i++) { a += shd[i]; b += shs[i]; }
        g_hpart[blockIdx.x][0] = a;
        g_hpart[blockIdx.x][1] = b;
    }
}

__global__ void finloss_kernel(float* __restrict__ out, int out_size) {
    __shared__ double sd[1024], sl[1024];
    int t = threadIdx.x;
    sd[t] = g_hpart[t][0]; sl[t] = g_hpart[t][1];
    __syncthreads();
    for (int o = 512; o; o >>= 1) {
        if (t < o) { sd[t] += sd[t + o]; sl[t] += sl[t + o]; }
        __syncthreads();
    }
    if (t == 0 && out_size > BATCH) {
        double ld = sd[0] / (double)BATCH;
        double ls = sl[0] / (double)BATCH;
        double bce = ld + ls;
        double wd = fmax(0.0, ld - bce);
        double ws = fmax(0.0, ls - bce);
        out[BATCH] = (float)(bce + wd * ld + ws * ls);
    }
}

// ---------------- host: derive fold_in keys ----------------
static void threefry2x32_host(uint32_t k0, uint32_t k1, uint32_t& x0, uint32_t& x1) {
    uint32_t k2 = k0 ^ k1 ^ 0x1BD11BDAu;
    x0 += k0; x1 += k1;
    auto rot = [](uint32_t v, int r) { return (v << r) | (v >> (32 - r)); };
    const int ra[4] = {13, 15, 26, 6}, rb[4] = {17, 29, 16, 24};
    auto four = [&](const int* rs) {
        for (int i = 0; i < 4; i++) { x0 += x1; x1 = rot(x1, rs[i]); x1 ^= x0; }
    };
    four(ra); x0 += k1; x1 += k2 + 1u;
    four(rb); x0 += k2; x1 += k0 + 2u;
    four(ra); x0 += k0; x1 += k1 + 3u;
    four(rb); x0 += k1; x1 += k2 + 4u;
    four(ra); x0 += k2; x1 += k0 + 5u;
}

extern "C" void kernel_launch(void* const* d_in, const int* in_sizes, int n_in,
                              void* d_out, int out_size) {
    const int*   xp = (const int*)d_in[0];
    const int*   xa = (const int*)d_in[1];
    const int*   xc = (const int*)d_in[2];
    const float* y_true = (const float*)d_in[3];
    const float* E0 = (const float*)d_in[4];
    const float* E1 = (const float*)d_in[5];
    const float* E2 = (const float*)d_in[6];
    const float* Wd = (const float*)d_in[7];
    const float* bd = (const float*)d_in[8];
    const float* Ws = (const float*)d_in[9];
    const float* bs = (const float*)d_in[10];
    const float* wfd = (const float*)d_in[11];
    const float* bfd = (const float*)d_in[12];
    const float* wfs = (const float*)d_in[13];
    const float* bfs = (const float*)d_in[14];
    float* out = (float*)d_out;

    // streams/events created ONCE (first call = correctness run, before the
    // pre-capture memory baseline) and reused on every subsequent call.
    static bool s_init = false;
    static cudaStream_t st[2];
    static cudaEvent_t evStart, evW, evFork, evJoin0, evJoin1;
    if (!s_init) {
        cudaStreamCreateWithFlags(&st[0], cudaStreamNonBlocking);
        cudaStreamCreateWithFlags(&st[1], cudaStreamNonBlocking);
        cudaEventCreateWithFlags(&evStart, cudaEventDisableTiming);
        cudaEventCreateWithFlags(&evW,     cudaEventDisableTiming);
        cudaEventCreateWithFlags(&evFork,  cudaEventDisableTiming);
        cudaEventCreateWithFlags(&evJoin0, cudaEventDisableTiming);
        cudaEventCreateWithFlags(&evJoin1, cudaEventDisableTiming);
        cudaFuncSetAttribute(gemm_kernel, cudaFuncAttributeMaxDynamicSharedMemorySize, GEMM_SMEM);
        s_init = true;
    }

    uint32_t keys[8][2];
    for (uint32_t t = 0; t < 8; t++) {
        uint32_t a = 0u, b = t;
        threefry2x32_host(0u, 42u, a, b);
        keys[t][0] = a; keys[t][1] = b;
    }

    // split_w on st[0] (forked off the origin stream) overlaps embed on stream 0
    cudaEventRecord(evStart, 0);
    cudaStreamWaitEvent(st[0], evStart, 0);
    split_w_kernel<<<2 * WSIZE / 4 / 256, 256, 0, st[0]>>>(Wd, Ws);
    cudaEventRecord(evW, st[0]);

    embed_kernel<<<NELEM / 4 / 256, 256>>>(xp, xa, xc, E0, E1, E2);
    cudaEventRecord(evFork, 0);

    cudaStreamWaitEvent(st[0], evFork, 0);     // st[0] already has evW in-stream
    cudaStreamWaitEvent(st[1], evFork, 0);
    cudaStreamWaitEvent(st[1], evW, 0);

    for (int net = 0; net < 2; net++) {
        for (int l = 0; l < NLAYERS; l++) {
            gemm_kernel<<<dim3(NTILES, MTILES / 2), 256, GEMM_SMEM, st[net]>>>(bd, bs, l, net);
            mask_kernel<<<NELEM / 4 / 256, 256, 0, st[net]>>>(keys[net * NLAYERS + l][0],
                                                              keys[net * NLAYERS + l][1],
                                                              net, l);
        }
    }
    cudaEventRecord(evJoin0, st[0]);
    cudaEventRecord(evJoin1, st[1]);
    cudaStreamWaitEvent(0, evJoin0, 0);
    cudaStreamWaitEvent(0, evJoin1, 0);

    head_kernel<<<BATCH / 8, 256>>>(wfd, wfs, bfd, bfs, y_true, out);
    finloss_kernel<<<1, 1024>>>(out, out_size);
}

// round 16
// speedup vs baseline: 1.2706x; 1.2706x over previous
#include <cuda_runtime.h>
#include <cuda_fp16.h>
#include <cstdint>
#include <math.h>

#define BATCH 8192
#define DIM 768
#define NELEM (BATCH * DIM)      /* 6291456 */
#define NLAYERS 4
#define WSIZE (NLAYERS * DIM * DIM)   /* 2359296 per net */

// GEMM tiling
#define BM 128
#define BN 64
#define BK 32
#define NCHUNKS (DIM / BK)       /* 24 */
#define NTILES (DIM / BN)        /* 12 */
#define MTILES (2 * BATCH / BM)  /* 128 total; 64 per net */
#define NSTAGES 3
#define STAGE_BYTES 24576
#define STAGE_HALVES 12288
#define GEMM_SMEM (NSTAGES * STAGE_BYTES)   /* 73728 */

#define OPSCALE 32.0f
#define INVSCALE (1.0f / 1024.0f)

// ---------------- device scratch ----------------
__device__ __align__(16) float  g_x[2 * (size_t)NELEM];
__device__ __align__(16) __half g_xhi[2 * (size_t)NELEM];
__device__ __align__(16) __half g_xlo[2 * (size_t)NELEM];
__device__ __align__(16) float  g_cross[2 * (size_t)NELEM];
__device__ double g_part[NTILES * MTILES][2];   /* 1536; net n at [n*768, n*768+768) */
__device__ float  g_mv[4];
__device__ double g_hpart[1024][2];
__device__ __align__(16) __half g_whi[2 * (size_t)WSIZE];
__device__ __align__(16) __half g_wlo[2 * (size_t)WSIZE];

// ---------------- helpers ----------------
__device__ __forceinline__ uint32_t smem_u32(const void* p) {
    uint32_t a;
    asm("{ .reg .u64 t; cvta.to.shared.u64 t, %1; cvt.u32.u64 %0, t; }" : "=r"(a) : "l"(p));
    return a;
}
#define CP_ASYNC16(dst, src) \
    asm volatile("cp.async.cg.shared.global [%0], [%1], 16;" :: "r"(dst), "l"(src) : "memory")
#define CP_COMMIT() asm volatile("cp.async.commit_group;" ::: "memory")
#define CP_WAIT(n)  asm volatile("cp.async.wait_group %0;" :: "n"(n) : "memory")

__device__ __forceinline__ uint32_t pack2(__half a, __half b) {
    __half2 h2 = __halves2half2(a, b);
    uint32_t u;
    asm("mov.b32 %0, %1;" : "=r"(u) : "r"(*reinterpret_cast<uint32_t*>(&h2)));
    return u;
}

__device__ __forceinline__ void split_f16(float v, __half& h, __half& l) {
    float vs = v * OPSCALE;
    h = __float2half_rn(vs);
    l = __float2half_rn(vs - __half2float(h));
}

__device__ __forceinline__ void mma_f16(float* d, const uint32_t* a, const uint32_t* b) {
    asm volatile(
        "mma.sync.aligned.m16n8k16.row.col.f32.f16.f16.f32 "
        "{%0,%1,%2,%3},{%4,%5,%6,%7},{%8,%9},{%0,%1,%2,%3};"
        : "+f"(d[0]), "+f"(d[1]), "+f"(d[2]), "+f"(d[3])
        : "r"(a[0]), "r"(a[1]), "r"(a[2]), "r"(a[3]), "r"(b[0]), "r"(b[1]));
}

__device__ __forceinline__ int sw_off(int r, int k) {
    return r * 32 + (k ^ ((r & 6) << 2));
}
__device__ __forceinline__ uint32_t ldh2(const __half* base, int r, int k) {
    return *reinterpret_cast<const uint32_t*>(base + sw_off(r, k));
}

// ---------------- W split (x4 vectorized) ----------------
__global__ void split_w_kernel(const float* __restrict__ Wd, const float* __restrict__ Ws) {
    size_t e = ((size_t)blockIdx.x * blockDim.x + threadIdx.x) * 4;
    if (e >= 2 * (size_t)WSIZE) return;
    float4 v = (e < WSIZE) ? *reinterpret_cast<const float4*>(Wd + e)
                           : *reinterpret_cast<const float4*>(Ws + (e - WSIZE));
    __half h0, h1, h2, h3, l0, l1, l2, l3;
    split_f16(v.x, h0, l0); split_f16(v.y, h1, l1);
    split_f16(v.z, h2, l2); split_f16(v.w, h3, l3);
    uint2 hh, ll;
    hh.x = pack2(h0, h1); hh.y = pack2(h2, h3);
    ll.x = pack2(l0, l1); ll.y = pack2(l2, l3);
    *reinterpret_cast<uint2*>(g_whi + e) = hh;
    *reinterpret_cast<uint2*>(g_wlo + e) = ll;
}

// ---------------- embedding gather + split (both nets) ----------------
__global__ void embed_kernel(const int* __restrict__ xp, const int* __restrict__ xa,
                             const int* __restrict__ xc,
                             const float* __restrict__ E0, const float* __restrict__ E1,
                             const float* __restrict__ E2) {
    int e = (blockIdx.x * blockDim.x + threadIdx.x) * 4;
    if (e >= NELEM) return;
    int b = e / DIM;
    int c = e - b * DIM;
    int s = c >> 7;
    int col = (c & 127) + ((s >= 3) ? 128 : 0);
    int t = (s >= 3) ? (s - 3) : s;
    int row;
    const float* E;
    if (t == 0)      { row = xp[b]; E = E0; }
    else if (t == 1) { row = xa[b]; E = E1; }
    else             { row = xc[b]; E = E2; }
    float4 v = *reinterpret_cast<const float4*>(E + (size_t)row * 256 + col);
    __half h0, h1, h2, h3, l0, l1, l2, l3;
    split_f16(v.x, h0, l0); split_f16(v.y, h1, l1);
    split_f16(v.z, h2, l2); split_f16(v.w, h3, l3);
    uint2 hh, ll;
    hh.x = pack2(h0, h1); hh.y = pack2(h2, h3);
    ll.x = pack2(l0, l1); ll.y = pack2(l2, l3);
    *reinterpret_cast<float4*>(g_x + e) = v;
    *reinterpret_cast<float4*>(g_x + (size_t)NELEM + e) = v;
    *reinterpret_cast<uint2*>(g_xhi + e) = hh;
    *reinterpret_cast<uint2*>(g_xhi + (size_t)NELEM + e) = hh;
    *reinterpret_cast<uint2*>(g_xlo + e) = ll;
    *reinterpret_cast<uint2*>(g_xlo + (size_t)NELEM + e) = ll;
}

// ---------------- mma.sync 3xFP16 GEMM, per-net grid (12 x 64), 2 CTAs/SM ----------------
__global__ __launch_bounds__(256, 2)
void gemm_kernel(const float* __restrict__ bd, const float* __restrict__ bs,
                 int layer, int net) {
    extern __shared__ __half smh[];
    const uint32_t sbase = smem_u32(smh);
    const int tid = threadIdx.x;
    const int wid = tid >> 5;
    const int lane = tid & 31;
    const int nt = blockIdx.x;
    const int mt = blockIdx.y + net * (MTILES / 2);
    const int mrow0 = mt * BM;
    const int nbase = nt * BN;
    const float* bias = (net ? bs : bd) + layer * DIM;
    const __half* Ahi_g = g_xhi + (size_t)mrow0 * DIM;
    const __half* Alo_g = g_xlo + (size_t)mrow0 * DIM;
    const __half* Bhi_g = g_whi + (size_t)(net * NLAYERS + layer) * DIM * DIM + (size_t)nbase * DIM;
    const __half* Blo_g = g_wlo + (size_t)(net * NLAYERS + layer) * DIM * DIM + (size_t)nbase * DIM;

    const int wm = wid >> 2;
    const int wn = wid & 3;

    float acc[4][2][4];
    #pragma unroll
    for (int t = 0; t < 4; t++)
        #pragma unroll
        for (int u = 0; u < 2; u++)
            #pragma unroll
            for (int j = 0; j < 4; j++) acc[t][u][j] = 0.0f;

    auto load_chunk = [&](int c, int stage) {
        uint32_t db = sbase + (uint32_t)stage * STAGE_BYTES;
        #pragma unroll
        for (int i = 0; i < 2; i++) {
            int id = tid + i * 256;
            int row = id >> 2, kg = id & 3;
            uint32_t soff = (uint32_t)(row * 64 + 16 * (kg ^ ((row & 6) >> 1)));
            size_t goff = (size_t)row * DIM + c * BK + kg * 8;
            CP_ASYNC16(db + soff,        Ahi_g + goff);
            CP_ASYNC16(db + 8192 + soff, Alo_g + goff);
        }
        {
            int row = tid >> 2, kg = tid & 3;
            uint32_t soff = (uint32_t)(row * 64 + 16 * (kg ^ ((row & 6) >> 1)));
            size_t goff = (size_t)row * DIM + c * BK + kg * 8;
            CP_ASYNC16(db + 16384 + soff, Bhi_g + goff);
            CP_ASYNC16(db + 20480 + soff, Blo_g + goff);
        }
        CP_COMMIT();
    };

    load_chunk(0, 0);
    load_chunk(1, 1);

    for (int c = 0; c < NCHUNKS; c++) {
        if (c + 1 < NCHUNKS) { CP_WAIT(1); } else { CP_WAIT(0); }
        __syncthreads();
        if (c + 2 < NCHUNKS) load_chunk(c + 2, (c + 2) % NSTAGES);

        const __half* Ah = smh + (c % NSTAGES) * STAGE_HALVES;
        const __half* Al = Ah + 4096;
        const __half* Bh = Ah + 8192;
        const __half* Bl = Ah + 10240;

        #pragma unroll
        for (int ks = 0; ks < 2; ks++) {
            const int kb = ks * 16 + 2 * (lane & 3);
            uint32_t ah[4][4], al[4][4], bh[2][2], bl[2][2];
            #pragma unroll
            for (int t = 0; t < 4; t++) {
                int r0 = wm * 64 + t * 16 + (lane >> 2);
                ah[t][0] = ldh2(Ah, r0,     kb);
                ah[t][1] = ldh2(Ah, r0 + 8, kb);
                ah[t][2] = ldh2(Ah, r0,     kb + 8);
                ah[t][3] = ldh2(Ah, r0 + 8, kb + 8);
                al[t][0] = ldh2(Al, r0,     kb);
                al[t][1] = ldh2(Al, r0 + 8, kb);
                al[t][2] = ldh2(Al, r0,     kb + 8);
                al[t][3] = ldh2(Al, r0 + 8, kb + 8);
            }
            #pragma unroll
            for (int u = 0; u < 2; u++) {
                int n0 = wn * 16 + u * 8 + (lane >> 2);
                bh[u][0] = ldh2(Bh, n0, kb);
                bh[u][1] = ldh2(Bh, n0, kb + 8);
                bl[u][0] = ldh2(Bl, n0, kb);
                bl[u][1] = ldh2(Bl, n0, kb + 8);
            }
            #pragma unroll
            for (int t = 0; t < 4; t++)
                #pragma unroll
                for (int u = 0; u < 2; u++) {
                    mma_f16(acc[t][u], ah[t], bh[u]);   // hi*hi
                    mma_f16(acc[t][u], ah[t], bl[u]);   // hi*lo
                    mma_f16(acc[t][u], al[t], bh[u]);   // lo*hi
                }
        }
        __syncthreads();
    }

    // ---- epilogue: unscale + bias -> g_cross, fused fp64 stats ----
    double s = 0.0, q = 0.0;
    #pragma unroll
    for (int t = 0; t < 4; t++) {
        int r0 = mrow0 + wm * 64 + t * 16 + (lane >> 2);
        #pragma unroll
        for (int u = 0; u < 2; u++) {
            int c0 = nbase + wn * 16 + u * 8 + 2 * (lane & 3);
            float b0 = __ldg(&bias[c0]), b1 = __ldg(&bias[c0 + 1]);
            float v0 = fmaf(acc[t][u][0], INVSCALE, b0);
            float v1 = fmaf(acc[t][u][1], INVSCALE, b1);
            float v2 = fmaf(acc[t][u][2], INVSCALE, b0);
            float v3 = fmaf(acc[t][u][3], INVSCALE, b1);
            *reinterpret_cast<float2*>(&g_cross[(size_t)r0 * DIM + c0])       = make_float2(v0, v1);
            *reinterpret_cast<float2*>(&g_cross[(size_t)(r0 + 8) * DIM + c0]) = make_float2(v2, v3);
            s += (double)v0 + (double)v1 + (double)v2 + (double)v3;
            q += (double)v0 * v0 + (double)v1 * v1 + (double)v2 * v2 + (double)v3 * v3;
        }
    }
    #pragma unroll
    for (int o = 16; o; o >>= 1) {
        s += __shfl_down_sync(~0u, s, o);
        q += __shfl_down_sync(~0u, q, o);
    }
    __shared__ double s_ps[8], s_pq[8];
    if (lane == 0) { s_ps[wid] = s; s_pq[wid] = q; }
    __syncthreads();
    if (tid == 0) {
        double S = 0, Q = 0;
        #pragma unroll
        for (int i = 0; i < 8; i++) { S += s_ps[i]; Q += s_pq[i]; }
        int cta = mt * NTILES + nt;
        g_part[cta][0] = S;
        g_part[cta][1] = Q;
    }
}

// ---------------- finalize stats for one net ----------------
__global__ void finstats_kernel(int net) {
    const int t = threadIdx.x;
    __shared__ double sh_s[8], sh_q[8];
    const int base = net * 768;
    double s = 0.0, q = 0.0;
    #pragma unroll
    for (int it = 0; it < 3; it++) {
        s += g_part[base + t + it * 256][0];
        q += g_part[base + t + it * 256][1];
    }
    #pragma unroll
    for (int o = 16; o; o >>= 1) {
        s += __shfl_down_sync(~0u, s, o);
        q += __shfl_down_sync(~0u, q, o);
    }
    int w = t >> 5, ln = t & 31;
    if (ln == 0) { sh_s[w] = s; sh_q[w] = q; }
    __syncthreads();
    if (t == 0) {
        double S = 0, Q = 0;
        #pragma unroll
        for (int j = 0; j < 8; j++) { S += sh_s[j]; Q += sh_q[j]; }
        double N = (double)NELEM;
        double m = S / N;
        float vf = (float)(Q / N - m * m);
        g_mv[net * 2 + 0] = (float)m;
        g_mv[net * 2 + 1] = (float)(1.0 / sqrt((double)vf + 1e-5));
    }
}

// ---------------- JAX Threefry2x32 (exact, 20 rounds), 4-wide ----------------
__device__ __forceinline__ void threefry4(uint32_t k0, uint32_t k1, unsigned i, uint32_t* bits) {
    uint32_t k2 = k0 ^ k1 ^ 0x1BD11BDAu;
    uint32_t a[4], b[4];
    #pragma unroll
    for (int j = 0; j < 4; j++) { a[j] = k0; b[j] = (i + j) + k1; }
#define TFR4(r) { _Pragma("unroll") for (int j = 0; j < 4; j++) { a[j] += b[j]; b[j] = __funnelshift_l(b[j], b[j], (r)); b[j] ^= a[j]; } }
#define KADD4(ka, kb, inc) { _Pragma("unroll") for (int j = 0; j < 4; j++) { a[j] += (ka); b[j] += (kb) + (inc); } }
    TFR4(13) TFR4(15) TFR4(26) TFR4(6)   KADD4(k1, k2, 1u)
    TFR4(17) TFR4(29) TFR4(16) TFR4(24)  KADD4(k2, k0, 2u)
    TFR4(13) TFR4(15) TFR4(26) TFR4(6)   KADD4(k0, k1, 3u)
    TFR4(17) TFR4(29) TFR4(16) TFR4(24)  KADD4(k1, k2, 4u)
    TFR4(13) TFR4(15) TFR4(26) TFR4(6)   KADD4(k2, k0, 5u)
#undef TFR4
#undef KADD4
    #pragma unroll
    for (int j = 0; j < 4; j++) bits[j] = a[j] ^ b[j];
}

// per-net mask: 4 elements per thread; `layer` controls last-layer split skip
__global__ void mask_kernel(uint32_t k0, uint32_t k1, int net, int layer) {
    unsigned v = blockIdx.x * blockDim.x + threadIdx.x;
    unsigned i = v * 4;                              // [0, NELEM)
    size_t e = (size_t)net * NELEM + i;
    uint32_t bits[4];
    threefry4(k0, k1, i, bits);
    float m = g_mv[net * 2], sc = g_mv[net * 2 + 1];
    float4 c4 = *reinterpret_cast<const float4*>(g_cross + e);
    float4 x4 = *reinterpret_cast<const float4*>(g_x + e);
    float cc[4] = {c4.x, c4.y, c4.z, c4.w};
    float xx[4] = {x4.x, x4.y, x4.z, x4.w};
    #pragma unroll
    for (int j = 0; j < 4; j++) {
        float p = __fdividef(1.0f, 1.0f + __expf(-(cc[j] - m) * sc));
        float u = __uint_as_float((bits[j] >> 9) | 0x3f800000u) - 1.0f;
        xx[j] += (u < p) ? cc[j] : 0.0f;
    }
    *reinterpret_cast<float4*>(g_x + e) = make_float4(xx[0], xx[1], xx[2], xx[3]);
    if (layer != NLAYERS - 1) {
        __half h0, h1, h2, h3, l0, l1, l2, l3;
        split_f16(xx[0], h0, l0); split_f16(xx[1], h1, l1);
        split_f16(xx[2], h2, l2); split_f16(xx[3], h3, l3);
        uint2 hh, ll;
        hh.x = pack2(h0, h1); hh.y = pack2(h2, h3);
        ll.x = pack2(l0, l1); ll.y = pack2(l2, l3);
        *reinterpret_cast<uint2*>(g_xhi + e) = hh;
        *reinterpret_cast<uint2*>(g_xlo + e) = ll;
    }
}

// ---------------- heads + per-row BCE terms ----------------
__device__ __forceinline__ float sigf(float x) { return 1.0f / (1.0f + expf(-x)); }

__global__ void head_kernel(const float* __restrict__ wfd, const float* __restrict__ wfs,
                            const float* __restrict__ bfd, const float* __restrict__ bfs,
                            const float* __restrict__ y_true, float* __restrict__ out) {
    int warp = threadIdx.x >> 5, lane = threadIdx.x & 31;
    int row = blockIdx.x * 8 + warp;
    const float* xd = g_x + (size_t)row * DIM;
    const float* xs = g_x + (size_t)NELEM + (size_t)row * DIM;
    float add = 0.f, ads = 0.f, asd = 0.f, ass = 0.f;
    for (int c = lane; c < DIM; c += 32) {
        float vd = xd[c], vs = xs[c], wd = wfd[c], ws = wfs[c];
        add = fmaf(vd, wd, add); ads = fmaf(vd, ws, ads);
        asd = fmaf(vs, wd, asd); ass = fmaf(vs, ws, ass);
    }
    #pragma unroll
    for (int o = 16; o; o >>= 1) {
        add += __shfl_down_sync(~0u, add, o);
        ads += __shfl_down_sync(~0u, ads, o);
        asd += __shfl_down_sync(~0u, asd, o);
        ass += __shfl_down_sync(~0u, ass, o);
    }
    __shared__ double shd[8], shs[8];
    if (lane == 0) {
        float sdd = sigf(add + bfd[0]);
        float sss = sigf(ass + bfs[0]);
        float sds = sigf(asd + bfd[0]);
        float ssd = sigf(ads + bfs[0]);
        float ypd = 0.5f * (sdd + sss);
        float yps = 0.5f * (sds + ssd);
        out[row] = ypd;
        float y = y_true[row];
        shd[warp] = (double)(-(y * logf(ypd) + (1.0f - y) * logf(1.0f - ypd)));
        shs[warp] = (double)(-(y * logf(yps) + (1.0f - y) * logf(1.0f - yps)));
    }
    __syncthreads();
    if (threadIdx.x == 0) {
        double a = 0, b = 0;
        #pragma unroll
        for (int i = 0; i < 8; i++) { a += shd[i]; b += shs[i]; }
        g_hpart[blockIdx.x][0] = a;
        g_hpart[blockIdx.x][1] = b;
    }
}

__global__ void finloss_kernel(float* __restrict__ out, int out_size) {
    __shared__ double sd[1024], sl[1024];
    int t = threadIdx.x;
    sd[t] = g_hpart[t][0]; sl[t] = g_hpart[t][1];
    __syncthreads();
    for (int o = 512; o; o >>= 1) {
        if (t < o) { sd[t] += sd[t + o]; sl[t] += sl[t + o]; }
        __syncthreads();
    }
    if (t == 0 && out_size > BATCH) {
        double ld = sd[0] / (double)BATCH;
        double ls = sl[0] / (double)BATCH;
        double bce = ld + ls;
        double wd = fmax(0.0, ld - bce);
        double ws = fmax(0.0, ls - bce);
        out[BATCH] = (float)(bce + wd * ld + ws * ls);
    }
}

// ---------------- host: derive fold_in keys ----------------
static void threefry2x32_host(uint32_t k0, uint32_t k1, uint32_t& x0, uint32_t& x1) {
    uint32_t k2 = k0 ^ k1 ^ 0x1BD11BDAu;
    x0 += k0; x1 += k1;
    auto rot = [](uint32_t v, int r) { return (v << r) | (v >> (32 - r)); };
    const int ra[4] = {13, 15, 26, 6}, rb[4] = {17, 29, 16, 24};
    auto four = [&](const int* rs) {
        for (int i = 0; i < 4; i++) { x0 += x1; x1 = rot(x1, rs[i]); x1 ^= x0; }
    };
    four(ra); x0 += k1; x1 += k2 + 1u;
    four(rb); x0 += k2; x1 += k0 + 2u;
    four(ra); x0 += k0; x1 += k1 + 3u;
    four(rb); x0 += k1; x1 += k2 + 4u;
    four(ra); x0 += k2; x1 += k0 + 5u;
}

extern "C" void kernel_launch(void* const* d_in, const int* in_sizes, int n_in,
                              void* d_out, int out_size) {
    const int*   xp = (const int*)d_in[0];
    const int*   xa = (const int*)d_in[1];
    const int*   xc = (const int*)d_in[2];
    const float* y_true = (const float*)d_in[3];
    const float* E0 = (const float*)d_in[4];
    const float* E1 = (const float*)d_in[5];
    const float* E2 = (const float*)d_in[6];
    const float* Wd = (const float*)d_in[7];
    const float* bd = (const float*)d_in[8];
    const float* Ws = (const float*)d_in[9];
    const float* bs = (const float*)d_in[10];
    const float* wfd = (const float*)d_in[11];
    const float* bfd = (const float*)d_in[12];
    const float* wfs = (const float*)d_in[13];
    const float* bfs = (const float*)d_in[14];
    float* out = (float*)d_out;

    // streams/events created ONCE (first call = correctness run, before the
    // pre-capture memory baseline) and reused on every subsequent call.
    static bool s_init = false;
    static cudaStream_t st[2];
    static cudaEvent_t evStart, evW, evFork, evJoin0, evJoin1;
    if (!s_init) {
        cudaStreamCreateWithFlags(&st[0], cudaStreamNonBlocking);
        cudaStreamCreateWithFlags(&st[1], cudaStreamNonBlocking);
        cudaEventCreateWithFlags(&evStart, cudaEventDisableTiming);
        cudaEventCreateWithFlags(&evW,     cudaEventDisableTiming);
        cudaEventCreateWithFlags(&evFork,  cudaEventDisableTiming);
        cudaEventCreateWithFlags(&evJoin0, cudaEventDisableTiming);
        cudaEventCreateWithFlags(&evJoin1, cudaEventDisableTiming);
        cudaFuncSetAttribute(gemm_kernel, cudaFuncAttributeMaxDynamicSharedMemorySize, GEMM_SMEM);
        s_init = true;
    }

    uint32_t keys[8][2];
    for (uint32_t t = 0; t < 8; t++) {
        uint32_t a = 0u, b = t;
        threefry2x32_host(0u, 42u, a, b);
        keys[t][0] = a; keys[t][1] = b;
    }

    // split_w on st[0] (forked off the origin stream) overlaps embed on stream 0
    cudaEventRecord(evStart, 0);
    cudaStreamWaitEvent(st[0], evStart, 0);
    split_w_kernel<<<2 * WSIZE / 4 / 256, 256, 0, st[0]>>>(Wd, Ws);
    cudaEventRecord(evW, st[0]);

    embed_kernel<<<NELEM / 4 / 256, 256>>>(xp, xa, xc, E0, E1, E2);
    cudaEventRecord(evFork, 0);

    cudaStreamWaitEvent(st[0], evFork, 0);     // st[0] already has evW in-stream
    cudaStreamWaitEvent(st[1], evFork, 0);
    cudaStreamWaitEvent(st[1], evW, 0);

    for (int net = 0; net < 2; net++) {
        for (int l = 0; l < NLAYERS; l++) {
            gemm_kernel<<<dim3(NTILES, MTILES / 2), 256, GEMM_SMEM, st[net]>>>(bd, bs, l, net);
            finstats_kernel<<<1, 256, 0, st[net]>>>(net);
            mask_kernel<<<NELEM / 4 / 256, 256, 0, st[net]>>>(keys[net * NLAYERS + l][0],
                                                              keys[net * NLAYERS + l][1],
                                                              net, l);
        }
    }
    cudaEventRecord(evJoin0, st[0]);
    cudaEventRecord(evJoin1, st[1]);
    cudaStreamWaitEvent(0, evJoin0, 0);
    cudaStreamWaitEvent(0, evJoin1, 0);

    head_kernel<<<BATCH / 8, 256>>>(wfd, wfs, bfd, bfs, y_true, out);
    finloss_kernel<<<1, 1024>>>(out, out_size);
}

// round 17
// speedup vs baseline: 1.2760x; 1.0043x over previous
#include <cuda_runtime.h>
#include <cuda_fp16.h>
#include <cstdint>
#include <math.h>

#define BATCH 8192
#define DIM 768
#define NELEM (BATCH * DIM)      /* 6291456 */
#define NLAYERS 4
#define WSIZE (NLAYERS * DIM * DIM)   /* 2359296 per net */

// GEMM tiling
#define BM 128
#define BN 64
#define BK 32
#define NCHUNKS (DIM / BK)       /* 24 */
#define NTILES (DIM / BN)        /* 12 */
#define MTILES (2 * BATCH / BM)  /* 128 total; 64 per net */
#define NSTAGES 4
#define STAGE_BYTES 24576
#define STAGE_HALVES 12288
#define GEMM_SMEM (NSTAGES * STAGE_BYTES)   /* 98304 */

#define OPSCALE 32.0f
#define INVSCALE (1.0f / 1024.0f)

// ---------------- device scratch ----------------
__device__ __align__(16) float  g_x[2 * (size_t)NELEM];
__device__ __align__(16) __half g_xhi[2 * (size_t)NELEM];
__device__ __align__(16) __half g_xlo[2 * (size_t)NELEM];
__device__ __align__(16) float  g_cross[2 * (size_t)NELEM];
__device__ double g_part[NTILES * MTILES][2];   /* 1536; net n at [n*768, n*768+768) */
__device__ float  g_mv[4];
__device__ double g_hpart[1024][2];
__device__ __align__(16) __half g_whi[2 * (size_t)WSIZE];
__device__ __align__(16) __half g_wlo[2 * (size_t)WSIZE];

// ---------------- helpers ----------------
__device__ __forceinline__ uint32_t smem_u32(const void* p) {
    uint32_t a;
    asm("{ .reg .u64 t; cvta.to.shared.u64 t, %1; cvt.u32.u64 %0, t; }" : "=r"(a) : "l"(p));
    return a;
}
#define CP_ASYNC16(dst, src) \
    asm volatile("cp.async.cg.shared.global [%0], [%1], 16;" :: "r"(dst), "l"(src) : "memory")
#define CP_COMMIT() asm volatile("cp.async.commit_group;" ::: "memory")
#define CP_WAIT(n)  asm volatile("cp.async.wait_group %0;" :: "n"(n) : "memory")

__device__ __forceinline__ uint32_t pack2(__half a, __half b) {
    __half2 h2 = __halves2half2(a, b);
    uint32_t u;
    asm("mov.b32 %0, %1;" : "=r"(u) : "r"(*reinterpret_cast<uint32_t*>(&h2)));
    return u;
}

__device__ __forceinline__ void split_f16(float v, __half& h, __half& l) {
    float vs = v * OPSCALE;
    h = __float2half_rn(vs);
    l = __float2half_rn(vs - __half2float(h));
}

__device__ __forceinline__ void mma_f16(float* d, const uint32_t* a, const uint32_t* b) {
    asm volatile(
        "mma.sync.aligned.m16n8k16.row.col.f32.f16.f16.f32 "
        "{%0,%1,%2,%3},{%4,%5,%6,%7},{%8,%9},{%0,%1,%2,%3};"
        : "+f"(d[0]), "+f"(d[1]), "+f"(d[2]), "+f"(d[3])
        : "r"(a[0]), "r"(a[1]), "r"(a[2]), "r"(a[3]), "r"(b[0]), "r"(b[1]));
}

__device__ __forceinline__ int sw_off(int r, int k) {
    return r * 32 + (k ^ ((r & 6) << 2));
}
__device__ __forceinline__ uint32_t ldh2(const __half* base, int r, int k) {
    return *reinterpret_cast<const uint32_t*>(base + sw_off(r, k));
}

// ---------------- W split (x4 vectorized) ----------------
__global__ void split_w_kernel(const float* __restrict__ Wd, const float* __restrict__ Ws) {
    size_t e = ((size_t)blockIdx.x * blockDim.x + threadIdx.x) * 4;
    if (e >= 2 * (size_t)WSIZE) return;
    float4 v = (e < WSIZE) ? *reinterpret_cast<const float4*>(Wd + e)
                           : *reinterpret_cast<const float4*>(Ws + (e - WSIZE));
    __half h0, h1, h2, h3, l0, l1, l2, l3;
    split_f16(v.x, h0, l0); split_f16(v.y, h1, l1);
    split_f16(v.z, h2, l2); split_f16(v.w, h3, l3);
    uint2 hh, ll;
    hh.x = pack2(h0, h1); hh.y = pack2(h2, h3);
    ll.x = pack2(l0, l1); ll.y = pack2(l2, l3);
    *reinterpret_cast<uint2*>(g_whi + e) = hh;
    *reinterpret_cast<uint2*>(g_wlo + e) = ll;
}

// ---------------- embedding gather + split (both nets) ----------------
__global__ void embed_kernel(const int* __restrict__ xp, const int* __restrict__ xa,
                             const int* __restrict__ xc,
                             const float* __restrict__ E0, const float* __restrict__ E1,
                             const float* __restrict__ E2) {
    int e = (blockIdx.x * blockDim.x + threadIdx.x) * 4;
    if (e >= NELEM) return;
    int b = e / DIM;
    int c = e - b * DIM;
    int s = c >> 7;
    int col = (c & 127) + ((s >= 3) ? 128 : 0);
    int t = (s >= 3) ? (s - 3) : s;
    int row;
    const float* E;
    if (t == 0)      { row = xp[b]; E = E0; }
    else if (t == 1) { row = xa[b]; E = E1; }
    else             { row = xc[b]; E = E2; }
    float4 v = *reinterpret_cast<const float4*>(E + (size_t)row * 256 + col);
    __half h0, h1, h2, h3, l0, l1, l2, l3;
    split_f16(v.x, h0, l0); split_f16(v.y, h1, l1);
    split_f16(v.z, h2, l2); split_f16(v.w, h3, l3);
    uint2 hh, ll;
    hh.x = pack2(h0, h1); hh.y = pack2(h2, h3);
    ll.x = pack2(l0, l1); ll.y = pack2(l2, l3);
    *reinterpret_cast<float4*>(g_x + e) = v;
    *reinterpret_cast<float4*>(g_x + (size_t)NELEM + e) = v;
    *reinterpret_cast<uint2*>(g_xhi + e) = hh;
    *reinterpret_cast<uint2*>(g_xhi + (size_t)NELEM + e) = hh;
    *reinterpret_cast<uint2*>(g_xlo + e) = ll;
    *reinterpret_cast<uint2*>(g_xlo + (size_t)NELEM + e) = ll;
}

// ---------------- mma.sync 3xFP16 GEMM, per-net grid (12 x 64), 2 CTAs/SM, 4 stages ----------------
__global__ __launch_bounds__(256, 2)
void gemm_kernel(const float* __restrict__ bd, const float* __restrict__ bs,
                 int layer, int net) {
    extern __shared__ __half smh[];
    const uint32_t sbase = smem_u32(smh);
    const int tid = threadIdx.x;
    const int wid = tid >> 5;
    const int lane = tid & 31;
    const int nt = blockIdx.x;
    const int mt = blockIdx.y + net * (MTILES / 2);
    const int mrow0 = mt * BM;
    const int nbase = nt * BN;
    const float* bias = (net ? bs : bd) + layer * DIM;
    const __half* Ahi_g = g_xhi + (size_t)mrow0 * DIM;
    const __half* Alo_g = g_xlo + (size_t)mrow0 * DIM;
    const __half* Bhi_g = g_whi + (size_t)(net * NLAYERS + layer) * DIM * DIM + (size_t)nbase * DIM;
    const __half* Blo_g = g_wlo + (size_t)(net * NLAYERS + layer) * DIM * DIM + (size_t)nbase * DIM;

    const int wm = wid >> 2;
    const int wn = wid & 3;

    float acc[4][2][4];
    #pragma unroll
    for (int t = 0; t < 4; t++)
        #pragma unroll
        for (int u = 0; u < 2; u++)
            #pragma unroll
            for (int j = 0; j < 4; j++) acc[t][u][j] = 0.0f;

    auto load_chunk = [&](int c, int stage) {
        uint32_t db = sbase + (uint32_t)stage * STAGE_BYTES;
        #pragma unroll
        for (int i = 0; i < 2; i++) {
            int id = tid + i * 256;
            int row = id >> 2, kg = id & 3;
            uint32_t soff = (uint32_t)(row * 64 + 16 * (kg ^ ((row & 6) >> 1)));
            size_t goff = (size_t)row * DIM + c * BK + kg * 8;
            CP_ASYNC16(db + soff,        Ahi_g + goff);
            CP_ASYNC16(db + 8192 + soff, Alo_g + goff);
        }
        {
            int row = tid >> 2, kg = tid & 3;
            uint32_t soff = (uint32_t)(row * 64 + 16 * (kg ^ ((row & 6) >> 1)));
            size_t goff = (size_t)row * DIM + c * BK + kg * 8;
            CP_ASYNC16(db + 16384 + soff, Bhi_g + goff);
            CP_ASYNC16(db + 20480 + soff, Blo_g + goff);
        }
        CP_COMMIT();
    };

    load_chunk(0, 0);
    load_chunk(1, 1);
    load_chunk(2, 2);

    for (int c = 0; c < NCHUNKS; c++) {
        if (c + 2 < NCHUNKS)      { CP_WAIT(2); }
        else if (c + 1 < NCHUNKS) { CP_WAIT(1); }
        else                      { CP_WAIT(0); }
        __syncthreads();
        if (c + 3 < NCHUNKS) load_chunk(c + 3, (c + 3) & 3);

        const __half* Ah = smh + (c & 3) * STAGE_HALVES;
        const __half* Al = Ah + 4096;
        const __half* Bh = Ah + 8192;
        const __half* Bl = Ah + 10240;

        #pragma unroll
        for (int ks = 0; ks < 2; ks++) {
            const int kb = ks * 16 + 2 * (lane & 3);
            uint32_t ah[4][4], al[4][4], bh[2][2], bl[2][2];
            #pragma unroll
            for (int t = 0; t < 4; t++) {
                int r0 = wm * 64 + t * 16 + (lane >> 2);
                ah[t][0] = ldh2(Ah, r0,     kb);
                ah[t][1] = ldh2(Ah, r0 + 8, kb);
                ah[t][2] = ldh2(Ah, r0,     kb + 8);
                ah[t][3] = ldh2(Ah, r0 + 8, kb + 8);
                al[t][0] = ldh2(Al, r0,     kb);
                al[t][1] = ldh2(Al, r0 + 8, kb);
                al[t][2] = ldh2(Al, r0,     kb + 8);
                al[t][3] = ldh2(Al, r0 + 8, kb + 8);
            }
            #pragma unroll
            for (int u = 0; u < 2; u++) {
                int n0 = wn * 16 + u * 8 + (lane >> 2);
                bh[u][0] = ldh2(Bh, n0, kb);
                bh[u][1] = ldh2(Bh, n0, kb + 8);
                bl[u][0] = ldh2(Bl, n0, kb);
                bl[u][1] = ldh2(Bl, n0, kb + 8);
            }
            #pragma unroll
            for (int t = 0; t < 4; t++)
                #pragma unroll
                for (int u = 0; u < 2; u++) {
                    mma_f16(acc[t][u], ah[t], bh[u]);   // hi*hi
                    mma_f16(acc[t][u], ah[t], bl[u]);   // hi*lo
                    mma_f16(acc[t][u], al[t], bh[u]);   // lo*hi
                }
        }
        __syncthreads();
    }

    // ---- epilogue: unscale + bias -> g_cross, fused fp64 stats ----
    double s = 0.0, q = 0.0;
    #pragma unroll
    for (int t = 0; t < 4; t++) {
        int r0 = mrow0 + wm * 64 + t * 16 + (lane >> 2);
        #pragma unroll
        for (int u = 0; u < 2; u++) {
            int c0 = nbase + wn * 16 + u * 8 + 2 * (lane & 3);
            float b0 = __ldg(&bias[c0]), b1 = __ldg(&bias[c0 + 1]);
            float v0 = fmaf(acc[t][u][0], INVSCALE, b0);
            float v1 = fmaf(acc[t][u][1], INVSCALE, b1);
            float v2 = fmaf(acc[t][u][2], INVSCALE, b0);
            float v3 = fmaf(acc[t][u][3], INVSCALE, b1);
            *reinterpret_cast<float2*>(&g_cross[(size_t)r0 * DIM + c0])       = make_float2(v0, v1);
            *reinterpret_cast<float2*>(&g_cross[(size_t)(r0 + 8) * DIM + c0]) = make_float2(v2, v3);
            s += (double)v0 + (double)v1 + (double)v2 + (double)v3;
            q += (double)v0 * v0 + (double)v1 * v1 + (double)v2 * v2 + (double)v3 * v3;
        }
    }
    #pragma unroll
    for (int o = 16; o; o >>= 1) {
        s += __shfl_down_sync(~0u, s, o);
        q += __shfl_down_sync(~0u, q, o);
    }
    __shared__ double s_ps[8], s_pq[8];
    if (lane == 0) { s_ps[wid] = s; s_pq[wid] = q; }
    __syncthreads();
    if (tid == 0) {
        double S = 0, Q = 0;
        #pragma unroll
        for (int i = 0; i < 8; i++) { S += s_ps[i]; Q += s_pq[i]; }
        int cta = mt * NTILES + nt;
        g_part[cta][0] = S;
        g_part[cta][1] = Q;
    }
}

// ---------------- finalize stats for one net ----------------
__global__ void finstats_kernel(int net) {
    const int t = threadIdx.x;
    __shared__ double sh_s[8], sh_q[8];
    const int base = net * 768;
    double s = 0.0, q = 0.0;
    #pragma unroll
    for (int it = 0; it < 3; it++) {
        s += g_part[base + t + it * 256][0];
        q += g_part[base + t + it * 256][1];
    }
    #pragma unroll
    for (int o = 16; o; o >>= 1) {
        s += __shfl_down_sync(~0u, s, o);
        q += __shfl_down_sync(~0u, q, o);
    }
    int w = t >> 5, ln = t & 31;
    if (ln == 0) { sh_s[w] = s; sh_q[w] = q; }
    __syncthreads();
    if (t == 0) {
        double S = 0, Q = 0;
        #pragma unroll
        for (int j = 0; j < 8; j++) { S += sh_s[j]; Q += sh_q[j]; }
        double N = (double)NELEM;
        double m = S / N;
        float vf = (float)(Q / N - m * m);
        g_mv[net * 2 + 0] = (float)m;
        g_mv[net * 2 + 1] = (float)(1.0 / sqrt((double)vf + 1e-5));
    }
}

// ---------------- JAX Threefry2x32 (exact, 20 rounds), 4-wide ----------------
__device__ __forceinline__ void threefry4(uint32_t k0, uint32_t k1, unsigned i, uint32_t* bits) {
    uint32_t k2 = k0 ^ k1 ^ 0x1BD11BDAu;
    uint32_t a[4], b[4];
    #pragma unroll
    for (int j = 0; j < 4; j++) { a[j] = k0; b[j] = (i + j) + k1; }
#define TFR4(r) { _Pragma("unroll") for (int j = 0; j < 4; j++) { a[j] += b[j]; b[j] = __funnelshift_l(b[j], b[j], (r)); b[j] ^= a[j]; } }
#define KADD4(ka, kb, inc) { _Pragma("unroll") for (int j = 0; j < 4; j++) { a[j] += (ka); b[j] += (kb) + (inc); } }
    TFR4(13) TFR4(15) TFR4(26) TFR4(6)   KADD4(k1, k2, 1u)
    TFR4(17) TFR4(29) TFR4(16) TFR4(24)  KADD4(k2, k0, 2u)
    TFR4(13) TFR4(15) TFR4(26) TFR4(6)   KADD4(k0, k1, 3u)
    TFR4(17) TFR4(29) TFR4(16) TFR4(24)  KADD4(k1, k2, 4u)
    TFR4(13) TFR4(15) TFR4(26) TFR4(6)   KADD4(k2, k0, 5u)
#undef TFR4
#undef KADD4
    #pragma unroll
    for (int j = 0; j < 4; j++) bits[j] = a[j] ^ b[j];
}

// per-net mask: 4 elements per thread; `layer` controls last-layer split skip
__global__ void mask_kernel(uint32_t k0, uint32_t k1, int net, int layer) {
    unsigned v = blockIdx.x * blockDim.x + threadIdx.x;
    unsigned i = v * 4;                              // [0, NELEM)
    size_t e = (size_t)net * NELEM + i;
    uint32_t bits[4];
    threefry4(k0, k1, i, bits);
    float m = g_mv[net * 2], sc = g_mv[net * 2 + 1];
    float4 c4 = *reinterpret_cast<const float4*>(g_cross + e);
    float4 x4 = *reinterpret_cast<const float4*>(g_x + e);
    float cc[4] = {c4.x, c4.y, c4.z, c4.w};
    float xx[4] = {x4.x, x4.y, x4.z, x4.w};
    #pragma unroll
    for (int j = 0; j < 4; j++) {
        float p = __fdividef(1.0f, 1.0f + __expf(-(cc[j] - m) * sc));
        float u = __uint_as_float((bits[j] >> 9) | 0x3f800000u) - 1.0f;
        xx[j] += (u < p) ? cc[j] : 0.0f;
    }
    *reinterpret_cast<float4*>(g_x + e) = make_float4(xx[0], xx[1], xx[2], xx[3]);
    if (layer != NLAYERS - 1) {
        __half h0, h1, h2, h3, l0, l1, l2, l3;
        split_f16(xx[0], h0, l0); split_f16(xx[1], h1, l1);
        split_f16(xx[2], h2, l2); split_f16(xx[3], h3, l3);
        uint2 hh, ll;
        hh.x = pack2(h0, h1); hh.y = pack2(h2, h3);
        ll.x = pack2(l0, l1); ll.y = pack2(l2, l3);
        *reinterpret_cast<uint2*>(g_xhi + e) = hh;
        *reinterpret_cast<uint2*>(g_xlo + e) = ll;
    }
}

// ---------------- heads + per-row BCE terms ----------------
__device__ __forceinline__ float sigf(float x) { return 1.0f / (1.0f + expf(-x)); }

__global__ void head_kernel(const float* __restrict__ wfd, const float* __restrict__ wfs,
                            const float* __restrict__ bfd, const float* __restrict__ bfs,
                            const float* __restrict__ y_true, float* __restrict__ out) {
    int warp = threadIdx.x >> 5, lane = threadIdx.x & 31;
    int row = blockIdx.x * 8 + warp;
    const float* xd = g_x + (size_t)row * DIM;
    const float* xs = g_x + (size_t)NELEM + (size_t)row * DIM;
    float add = 0.f, ads = 0.f, asd = 0.f, ass = 0.f;
    for (int c = lane; c < DIM; c += 32) {
        float vd = xd[c], vs = xs[c], wd = wfd[c], ws = wfs[c];
        add = fmaf(vd, wd, add); ads = fmaf(vd, ws, ads);
        asd = fmaf(vs, wd, asd); ass = fmaf(vs, ws, ass);
    }
    #pragma unroll
    for (int o = 16; o; o >>= 1) {
        add += __shfl_down_sync(~0u, add, o);
        ads += __shfl_down_sync(~0u, ads, o);
        asd += __shfl_down_sync(~0u, asd, o);
        ass += __shfl_down_sync(~0u, ass, o);
    }
    __shared__ double shd[8], shs[8];
    if (lane == 0) {
        float sdd = sigf(add + bfd[0]);
        float sss = sigf(ass + bfs[0]);
        float sds = sigf(asd + bfd[0]);
        float ssd = sigf(ads + bfs[0]);
        float ypd = 0.5f * (sdd + sss);
        float yps = 0.5f * (sds + ssd);
        out[row] = ypd;
        float y = y_true[row];
        shd[warp] = (double)(-(y * logf(ypd) + (1.0f - y) * logf(1.0f - ypd)));
        shs[warp] = (double)(-(y * logf(yps) + (1.0f - y) * logf(1.0f - yps)));
    }
    __syncthreads();
    if (threadIdx.x == 0) {
        double a = 0, b = 0;
        #pragma unroll
        for (int i = 0; i < 8; i++) { a += shd[i]; b += shs[i]; }
        g_hpart[blockIdx.x][0] = a;
        g_hpart[blockIdx.x][1] = b;
    }
}

__global__ void finloss_kernel(float* __restrict__ out, int out_size) {
    __shared__ double sd[1024], sl[1024];
    int t = threadIdx.x;
    sd[t] = g_hpart[t][0]; sl[t] = g_hpart[t][1];
    __syncthreads();
    for (int o = 512; o; o >>= 1) {
        if (t < o) { sd[t] += sd[t + o]; sl[t] += sl[t + o]; }
        __syncthreads();
    }
    if (t == 0 && out_size > BATCH) {
        double ld = sd[0] / (double)BATCH;
        double ls = sl[0] / (double)BATCH;
        double bce = ld + ls;
        double wd = fmax(0.0, ld - bce);
        double ws = fmax(0.0, ls - bce);
        out[BATCH] = (float)(bce + wd * ld + ws * ls);
    }
}

// ---------------- host: derive fold_in keys ----------------
static void threefry2x32_host(uint32_t k0, uint32_t k1, uint32_t& x0, uint32_t& x1) {
    uint32_t k2 = k0 ^ k1 ^ 0x1BD11BDAu;
    x0 += k0; x1 += k1;
    auto rot = [](uint32_t v, int r) { return (v << r) | (v >> (32 - r)); };
    const int ra[4] = {13, 15, 26, 6}, rb[4] = {17, 29, 16, 24};
    auto four = [&](const int* rs) {
        for (int i = 0; i < 4; i++) { x0 += x1; x1 = rot(x1, rs[i]); x1 ^= x0; }
    };
    four(ra); x0 += k1; x1 += k2 + 1u;
    four(rb); x0 += k2; x1 += k0 + 2u;
    four(ra); x0 += k0; x1 += k1 + 3u;
    four(rb); x0 += k1; x1 += k2 + 4u;
    four(ra); x0 += k2; x1 += k0 + 5u;
}

extern "C" void kernel_launch(void* const* d_in, const int* in_sizes, int n_in,
                              void* d_out, int out_size) {
    const int*   xp = (const int*)d_in[0];
    const int*   xa = (const int*)d_in[1];
    const int*   xc = (const int*)d_in[2];
    const float* y_true = (const float*)d_in[3];
    const float* E0 = (const float*)d_in[4];
    const float* E1 = (const float*)d_in[5];
    const float* E2 = (const float*)d_in[6];
    const float* Wd = (const float*)d_in[7];
    const float* bd = (const float*)d_in[8];
    const float* Ws = (const float*)d_in[9];
    const float* bs = (const float*)d_in[10];
    const float* wfd = (const float*)d_in[11];
    const float* bfd = (const float*)d_in[12];
    const float* wfs = (const float*)d_in[13];
    const float* bfs = (const float*)d_in[14];
    float* out = (float*)d_out;

    // streams/events created ONCE (first call = correctness run, before the
    // pre-capture memory baseline) and reused on every subsequent call.
    static bool s_init = false;
    static cudaStream_t st[2];
    static cudaEvent_t evStart, evW, evFork, evJoin0, evJoin1;
    if (!s_init) {
        cudaStreamCreateWithFlags(&st[0], cudaStreamNonBlocking);
        cudaStreamCreateWithFlags(&st[1], cudaStreamNonBlocking);
        cudaEventCreateWithFlags(&evStart, cudaEventDisableTiming);
        cudaEventCreateWithFlags(&evW,     cudaEventDisableTiming);
        cudaEventCreateWithFlags(&evFork,  cudaEventDisableTiming);
        cudaEventCreateWithFlags(&evJoin0, cudaEventDisableTiming);
        cudaEventCreateWithFlags(&evJoin1, cudaEventDisableTiming);
        cudaFuncSetAttribute(gemm_kernel, cudaFuncAttributeMaxDynamicSharedMemorySize, GEMM_SMEM);
        s_init = true;
    }

    uint32_t keys[8][2];
    for (uint32_t t = 0; t < 8; t++) {
        uint32_t a = 0u, b = t;
        threefry2x32_host(0u, 42u, a, b);
        keys[t][0] = a; keys[t][1] = b;
    }

    // split_w on st[0] (forked off the origin stream) overlaps embed on stream 0
    cudaEventRecord(evStart, 0);
    cudaStreamWaitEvent(st[0], evStart, 0);
    split_w_kernel<<<2 * WSIZE / 4 / 256, 256, 0, st[0]>>>(Wd, Ws);
    cudaEventRecord(evW, st[0]);

    embed_kernel<<<NELEM / 4 / 256, 256>>>(xp, xa, xc, E0, E1, E2);
    cudaEventRecord(evFork, 0);

    cudaStreamWaitEvent(st[0], evFork, 0);
    cudaStreamWaitEvent(st[1], evFork, 0);
    cudaStreamWaitEvent(st[1], evW, 0);

    for (int net = 0; net < 2; net++) {
        for (int l = 0; l < NLAYERS; l++) {
            gemm_kernel<<<dim3(NTILES, MTILES / 2), 256, GEMM_SMEM, st[net]>>>(bd, bs, l, net);
            finstats_kernel<<<1, 256, 0, st[net]>>>(net);
            mask_kernel<<<NELEM / 4 / 256, 256, 0, st[net]>>>(keys[net * NLAYERS + l][0],
                                                              keys[net * NLAYERS + l][1],
                                                              net, l);
        }
    }
    cudaEventRecord(evJoin0, st[0]);
    cudaEventRecord(evJoin1, st[1]);
    cudaStreamWaitEvent(0, evJoin0, 0);
    cudaStreamWaitEvent(0, evJoin1, 0);

    head_kernel<<<BATCH / 8, 256>>>(wfd, wfs, bfd, bfs, y_true, out);
    finloss_kernel<<<1, 1024>>>(out, out_size);
}